// round 2
// baseline (speedup 1.0000x reference)
#include <cuda_runtime.h>
#include <math.h>

// Problem dims (fixed)
#define BB 2
#define SS 2048
#define DD 1024
#define LL 1024
#define HH 16
#define DHH 64
#define NTOK 4096   // BB*SS
#define BHN 32      // BB*HH

// ---------------- scratch (static device globals; no allocations) ------------
__device__ float g_q [(size_t)NTOK * LL];
__device__ float g_k [(size_t)NTOK * LL];
__device__ float g_v [(size_t)NTOK * LL];
__device__ float g_sc[(size_t)BHN * SS * SS];   // 512 MB scores/attn
__device__ float g_z1[(size_t)NTOK * DD];
__device__ float g_z2[(size_t)NTOK * DD];
__device__ float g_z3[(size_t)NTOK * DD];

// ---------------- 128x128x8 register-blocked SGEMM (row-major NN) ------------
// C[M,N] = A[M,K] @ B[K,N].  M%128==0, N%128==0, K%8==0 required.
__global__ __launch_bounds__(256) void sgemm_nn_128(
    const float* __restrict__ A, const float* __restrict__ Bm, float* __restrict__ C,
    int M, int N, int K)
{
    __shared__ float As[8][128];
    __shared__ float Bs[8][128];
    int tid = threadIdx.x;
    int bx = blockIdx.x, by = blockIdx.y;
    const float* Ab = A + (size_t)by * 128 * K;
    const float* Bb = Bm + (size_t)bx * 128;

    float acc[8][8];
#pragma unroll
    for (int i = 0; i < 8; i++)
#pragma unroll
        for (int j = 0; j < 8; j++) acc[i][j] = 0.f;

    int aRow = tid >> 1, aCol = (tid & 1) * 4;   // 128 rows x 8 cols (float4)
    int bRow = tid >> 5, bCol = (tid & 31) * 4;  // 8 rows x 128 cols (float4)
    int tr = tid >> 4, tc = tid & 15;            // 16x16 threads, 8x8 each

    for (int k0 = 0; k0 < K; k0 += 8) {
        float4 a4 = *reinterpret_cast<const float4*>(Ab + (size_t)aRow * K + k0 + aCol);
        As[aCol + 0][aRow] = a4.x;
        As[aCol + 1][aRow] = a4.y;
        As[aCol + 2][aRow] = a4.z;
        As[aCol + 3][aRow] = a4.w;
        *reinterpret_cast<float4*>(&Bs[bRow][bCol]) =
            *reinterpret_cast<const float4*>(Bb + (size_t)(k0 + bRow) * N + bCol);
        __syncthreads();
#pragma unroll
        for (int k = 0; k < 8; k++) {
            float ra[8], rb[8];
#pragma unroll
            for (int i = 0; i < 8; i++) ra[i] = As[k][tr * 8 + i];
#pragma unroll
            for (int j = 0; j < 8; j++) rb[j] = Bs[k][tc * 8 + j];
#pragma unroll
            for (int i = 0; i < 8; i++)
#pragma unroll
                for (int j = 0; j < 8; j++) acc[i][j] = fmaf(ra[i], rb[j], acc[i][j]);
        }
        __syncthreads();
    }
#pragma unroll
    for (int i = 0; i < 8; i++) {
        float* Cr = C + (size_t)(by * 128 + tr * 8 + i) * N + bx * 128 + tc * 8;
        *reinterpret_cast<float4*>(Cr)     = make_float4(acc[i][0], acc[i][1], acc[i][2], acc[i][3]);
        *reinterpret_cast<float4*>(Cr + 4) = make_float4(acc[i][4], acc[i][5], acc[i][6], acc[i][7]);
    }
}

// ---------------- scores[bh][k][q] = (K_row . Q_row) / 32 --------------------
// Batched NT GEMM: per head, C[m=k_idx][n=q_idx] = sum_d K[m,d]*Q[n,d] * scale
__global__ __launch_bounds__(256) void attn_scores_k(
    const float* __restrict__ gk, const float* __restrict__ gq, float* __restrict__ sc)
{
    int bh = blockIdx.z;
    int b = bh >> 4, h = bh & 15;
    const float* Kp = gk + (size_t)b * SS * LL + h * DHH;
    const float* Qp = gq + (size_t)b * SS * LL + h * DHH;
    float* Cp = sc + (size_t)bh * SS * SS;

    __shared__ float Ks[64][65];
    __shared__ float Qs[64][65];
    int tid = threadIdx.x;
    int m0 = blockIdx.y * 64, n0 = blockIdx.x * 64;
    int lr = tid >> 4, lc = (tid & 15) * 4;

#pragma unroll
    for (int r = lr; r < 64; r += 16) {
        float4 a4 = *reinterpret_cast<const float4*>(Kp + (size_t)(m0 + r) * LL + lc);
        Ks[r][lc] = a4.x; Ks[r][lc + 1] = a4.y; Ks[r][lc + 2] = a4.z; Ks[r][lc + 3] = a4.w;
        float4 b4 = *reinterpret_cast<const float4*>(Qp + (size_t)(n0 + r) * LL + lc);
        Qs[r][lc] = b4.x; Qs[r][lc + 1] = b4.y; Qs[r][lc + 2] = b4.z; Qs[r][lc + 3] = b4.w;
    }
    __syncthreads();

    int tr = tid >> 4, tc = tid & 15;
    float acc[4][4];
#pragma unroll
    for (int i = 0; i < 4; i++)
#pragma unroll
        for (int j = 0; j < 4; j++) acc[i][j] = 0.f;

#pragma unroll 8
    for (int d = 0; d < 64; d++) {
        float ra[4], rb[4];
#pragma unroll
        for (int i = 0; i < 4; i++) ra[i] = Ks[tr * 4 + i][d];
#pragma unroll
        for (int j = 0; j < 4; j++) rb[j] = Qs[tc * 4 + j][d];
#pragma unroll
        for (int i = 0; i < 4; i++)
#pragma unroll
            for (int j = 0; j < 4; j++) acc[i][j] = fmaf(ra[i], rb[j], acc[i][j]);
    }
    const float scale = 0.03125f;  // 1/sqrt(1024)
#pragma unroll
    for (int i = 0; i < 4; i++) {
        float4 o = make_float4(acc[i][0] * scale, acc[i][1] * scale,
                               acc[i][2] * scale, acc[i][3] * scale);
        *reinterpret_cast<float4*>(Cp + (size_t)(m0 + tr * 4 + i) * SS + n0 + tc * 4) = o;
    }
}

// ---------------- row softmax over contiguous rows of length 2048 ------------
__global__ __launch_bounds__(256) void softmax_k(float* __restrict__ sc)
{
    size_t row = blockIdx.x;
    float* p = sc + row * (size_t)SS;
    int tid = threadIdx.x;
    float v[8];
    float m = -1e30f;
#pragma unroll
    for (int i = 0; i < 8; i++) { v[i] = p[tid + i * 256]; m = fmaxf(m, v[i]); }
    __shared__ float red[256];
    red[tid] = m; __syncthreads();
    for (int s2 = 128; s2 > 0; s2 >>= 1) {
        if (tid < s2) red[tid] = fmaxf(red[tid], red[tid + s2]);
        __syncthreads();
    }
    m = red[0]; __syncthreads();
    float sum = 0.f;
#pragma unroll
    for (int i = 0; i < 8; i++) { v[i] = expf(v[i] - m); sum += v[i]; }
    red[tid] = sum; __syncthreads();
    for (int s2 = 128; s2 > 0; s2 >>= 1) {
        if (tid < s2) red[tid] += red[tid + s2];
        __syncthreads();
    }
    float inv = 1.0f / red[0];
#pragma unroll
    for (int i = 0; i < 8; i++) p[tid + i * 256] = v[i] * inv;
}

// ---------------- out[bh][q][v] = sum_k attn[bh][k][q] * V[b][k][h][v] -------
// TN GEMM: C[m=q, n=v] = sum_kk A[kk][m] * B[kk][n].
__global__ __launch_bounds__(256) void attn_out_k(
    const float* __restrict__ attn, const float* __restrict__ gv, float* __restrict__ z)
{
    int bh = blockIdx.z;
    int b = bh >> 4, h = bh & 15;
    const float* Ap = attn + (size_t)bh * SS * SS;
    const float* Vp = gv + (size_t)b * SS * LL + h * DHH;
    float* Cp = z + (size_t)b * SS * DD + h * DHH;
    int m0 = blockIdx.x * 64;

    __shared__ float As[16][64];
    __shared__ float Bs[16][64];
    int tid = threadIdx.x;
    int lr = tid >> 4, lc = (tid & 15) * 4;
    int tr = tid >> 4, tc = tid & 15;

    float acc[4][4];
#pragma unroll
    for (int i = 0; i < 4; i++)
#pragma unroll
        for (int j = 0; j < 4; j++) acc[i][j] = 0.f;

    for (int k0 = 0; k0 < SS; k0 += 16) {
        *reinterpret_cast<float4*>(&As[lr][lc]) =
            *reinterpret_cast<const float4*>(Ap + (size_t)(k0 + lr) * SS + m0 + lc);
        *reinterpret_cast<float4*>(&Bs[lr][lc]) =
            *reinterpret_cast<const float4*>(Vp + (size_t)(k0 + lr) * LL + lc);
        __syncthreads();
#pragma unroll
        for (int kk = 0; kk < 16; kk++) {
            float ra[4], rb[4];
#pragma unroll
            for (int i = 0; i < 4; i++) ra[i] = As[kk][tr * 4 + i];
#pragma unroll
            for (int j = 0; j < 4; j++) rb[j] = Bs[kk][tc * 4 + j];
#pragma unroll
            for (int i = 0; i < 4; i++)
#pragma unroll
                for (int j = 0; j < 4; j++) acc[i][j] = fmaf(ra[i], rb[j], acc[i][j]);
        }
        __syncthreads();
    }
#pragma unroll
    for (int i = 0; i < 4; i++) {
        *reinterpret_cast<float4*>(Cp + (size_t)(m0 + tr * 4 + i) * DD + tc * 4) =
            make_float4(acc[i][0], acc[i][1], acc[i][2], acc[i][3]);
    }
}

// ---------------- L2 row-normalize (rows of 1024) ----------------------------
__global__ __launch_bounds__(256) void l2norm_k(const float* __restrict__ in, float* __restrict__ out)
{
    size_t row = blockIdx.x;
    const float* p = in + row * (size_t)DD;
    float* o = out + row * (size_t)DD;
    int tid = threadIdx.x;
    float4 v = *reinterpret_cast<const float4*>(p + tid * 4);
    float ss = v.x * v.x + v.y * v.y + v.z * v.z + v.w * v.w;
    __shared__ float red[256];
    red[tid] = ss; __syncthreads();
    for (int s2 = 128; s2 > 0; s2 >>= 1) {
        if (tid < s2) red[tid] += red[tid + s2];
        __syncthreads();
    }
    float inv = 1.0f / fmaxf(sqrtf(red[0]), 1e-12f);
    *reinterpret_cast<float4*>(o + tid * 4) =
        make_float4(v.x * inv, v.y * inv, v.z * inv, v.w * inv);
}

// ---------------- L2 row-normalize + exact-erf GELU --------------------------
__device__ __forceinline__ float gelu_exact(float x)
{
    return 0.5f * x * (1.0f + erff(x * 0.7071067811865475f));
}

__global__ __launch_bounds__(256) void l2norm_gelu_k(const float* __restrict__ in, float* __restrict__ out)
{
    size_t row = blockIdx.x;
    const float* p = in + row * (size_t)DD;
    float* o = out + row * (size_t)DD;
    int tid = threadIdx.x;
    float4 v = *reinterpret_cast<const float4*>(p + tid * 4);
    float ss = v.x * v.x + v.y * v.y + v.z * v.z + v.w * v.w;
    __shared__ float red[256];
    red[tid] = ss; __syncthreads();
    for (int s2 = 128; s2 > 0; s2 >>= 1) {
        if (tid < s2) red[tid] += red[tid + s2];
        __syncthreads();
    }
    float inv = 1.0f / fmaxf(sqrtf(red[0]), 1e-12f);
    *reinterpret_cast<float4*>(o + tid * 4) =
        make_float4(gelu_exact(v.x * inv), gelu_exact(v.y * inv),
                    gelu_exact(v.z * inv), gelu_exact(v.w * inv));
}

// ---------------- launch ------------------------------------------------------
extern "C" void kernel_launch(void* const* d_in, const int* in_sizes, int n_in,
                              void* d_out, int out_size)
{
    const float* x   = (const float*)d_in[0];
    const float* Wq  = (const float*)d_in[1];
    const float* Wk  = (const float*)d_in[2];
    const float* Wv  = (const float*)d_in[3];
    const float* Wo  = (const float*)d_in[4];
    const float* Wff = (const float*)d_in[5];
    float* out = (float*)d_out;

    float *q, *k, *v, *sc, *z1, *z2, *z3;
    cudaGetSymbolAddress((void**)&q,  g_q);
    cudaGetSymbolAddress((void**)&k,  g_k);
    cudaGetSymbolAddress((void**)&v,  g_v);
    cudaGetSymbolAddress((void**)&sc, g_sc);
    cudaGetSymbolAddress((void**)&z1, g_z1);
    cudaGetSymbolAddress((void**)&z2, g_z2);
    cudaGetSymbolAddress((void**)&z3, g_z3);

    dim3 gnn(LL / 128, NTOK / 128);  // (8, 32)

    // QKV projections
    sgemm_nn_128<<<gnn, 256>>>(x, Wq, q, NTOK, LL, DD);
    sgemm_nn_128<<<gnn, 256>>>(x, Wk, k, NTOK, LL, DD);
    sgemm_nn_128<<<gnn, 256>>>(x, Wv, v, NTOK, LL, DD);

    // scores[bh][k][q] = K.Q^T / 32
    dim3 gsc(SS / 64, SS / 64, BHN);  // (32, 32, 32)
    attn_scores_k<<<gsc, 256>>>(k, q, sc);

    // softmax over q axis (contiguous rows)
    softmax_k<<<BHN * SS, 256>>>(sc);

    // out = attn^T @ V, merged-head layout
    dim3 gao(SS / 64, 1, BHN);  // (32, 1, 32)
    attn_out_k<<<gao, 256>>>(sc, v, z1);

    // output projection, normalize, FF, normalize+gelu
    sgemm_nn_128<<<gnn, 256>>>(z1, Wo, z2, NTOK, DD, LL);
    l2norm_k<<<NTOK, 256>>>(z2, z2);
    sgemm_nn_128<<<gnn, 256>>>(z2, Wff, z3, NTOK, DD, DD);
    l2norm_gelu_k<<<NTOK, 256>>>(z3, out);
}